// round 5
// baseline (speedup 1.0000x reference)
#include <cuda_runtime.h>
#include <cstdint>

typedef unsigned long long ull;

// ---------------- scratch (device globals; no runtime allocation) ----------------
__device__ float g_xn   [8u*4096u*256u];          // LayerNorm output  [B*L, C]
__device__ float g_qkv  [8u*4096u*768u];          // QKV               [B*L, 3C]
__device__ float g_xcat2[8u*4096u*256u];          // pre-proj, token-major [B*L, C'] (head-grouped)
__device__ float g_pw2  [256u*256u];              // proj weights, K permuted to match g_xcat2
__device__ float g_attn_fb[2u*128u*4u*256u*256u]; // fallback attn store

// ---------------- packed f32x2 helpers ----------------
__device__ __forceinline__ ull ffma2(ull a, ull b, ull c) {
    ull d;
    asm("fma.rn.f32x2 %0, %1, %2, %3;" : "=l"(d) : "l"(a), "l"(b), "l"(c));
    return d;
}
__device__ __forceinline__ ull pack2(float x, float y) {
    ull r; asm("mov.b64 %0, {%1, %2};" : "=l"(r) : "f"(x), "f"(y)); return r;
}
__device__ __forceinline__ ull dup2(float x) { return pack2(x, x); }
__device__ __forceinline__ float2 unpack2(ull v) {
    float2 f; asm("mov.b64 {%0, %1}, %2;" : "=f"(f.x), "=f"(f.y) : "l"(v)); return f;
}

// ---------------- Kernel 1: transpose + LayerNorm ----------------
__global__ void ln_kernel(const float* __restrict__ x,
                          const float* __restrict__ gam,
                          const float* __restrict__ bet) {
    __shared__ float s[32][257];
    int bb    = blockIdx.x >> 7;
    int lbase = (blockIdx.x & 127) << 5;
    int tx = threadIdx.x, ty = threadIdx.y;
    const float* xb = x + (size_t)bb * 256 * 4096;
    #pragma unroll
    for (int i = 0; i < 8; ++i) {
        int cc = ty + (i << 5);
        s[tx][cc] = xb[(size_t)cc * 4096 + lbase + tx];
    }
    __syncthreads();
    float v[8], sum = 0.f, sq = 0.f;
    #pragma unroll
    for (int i = 0; i < 8; ++i) {
        v[i] = s[ty][tx + (i << 5)];
        sum += v[i]; sq += v[i] * v[i];
    }
    #pragma unroll
    for (int o = 16; o; o >>= 1) {
        sum += __shfl_xor_sync(0xffffffffu, sum, o);
        sq  += __shfl_xor_sync(0xffffffffu, sq,  o);
    }
    float mean = sum * (1.f / 256.f);
    float var  = sq  * (1.f / 256.f) - mean * mean;
    float rstd = rsqrtf(var + 1e-4f);
    float* op = g_xn + (size_t)(bb * 4096 + lbase + ty) * 256;
    #pragma unroll
    for (int i = 0; i < 8; ++i) {
        int cc = tx + (i << 5);
        op[cc] = (v[i] - mean) * rstd * gam[cc] + bet[cc];
    }
}

// ---------------- Kernel 2: QKV GEMM (f32x2, double-buffered) ----------------
// g_qkv[m,n] = sum_k g_xn[m,k] * W[n,k];  M=32768, N=768, K=256
__global__ __launch_bounds__(256, 2) void gemm_qkv(const float* __restrict__ W) {
    __shared__ float As[2][16][128];
    __shared__ float Bs[2][16][128];
    int n0 = blockIdx.x << 7, m0 = blockIdx.y << 7;
    int tid = threadIdx.x;
    int tm = (tid >> 4) << 3, tn = (tid & 15) << 3;
    int lr = tid >> 2;            // fill row (two iters: +64)
    int lk = (tid & 3) << 2;      // fill k quad
    ull acc[4][8];
    #pragma unroll
    for (int i = 0; i < 4; ++i)
        #pragma unroll
        for (int j = 0; j < 8; ++j) acc[i][j] = 0ull;

    const float* Ab = g_xn + (size_t)m0 * 256;
    const float* Bb = W    + (size_t)n0 * 256;

    #pragma unroll
    for (int i = 0; i < 2; ++i) {
        int r = lr + (i << 6);
        float4 va = *(const float4*)(Ab + (size_t)r * 256 + lk);
        As[0][lk+0][r] = va.x; As[0][lk+1][r] = va.y; As[0][lk+2][r] = va.z; As[0][lk+3][r] = va.w;
        float4 vb = *(const float4*)(Bb + (size_t)r * 256 + lk);
        Bs[0][lk+0][r] = vb.x; Bs[0][lk+1][r] = vb.y; Bs[0][lk+2][r] = vb.z; Bs[0][lk+3][r] = vb.w;
    }
    __syncthreads();

    for (int kc = 0; kc < 16; ++kc) {
        int cur = kc & 1;
        float4 pa[2], pb[2];
        if (kc < 15) {
            int k0 = (kc + 1) << 4;
            #pragma unroll
            for (int i = 0; i < 2; ++i) {
                int r = lr + (i << 6);
                pa[i] = *(const float4*)(Ab + (size_t)r * 256 + k0 + lk);
                pb[i] = *(const float4*)(Bb + (size_t)r * 256 + k0 + lk);
            }
        }
        #pragma unroll
        for (int k = 0; k < 16; ++k) {
            ulonglong2 a01 = *(const ulonglong2*)&As[cur][k][tm];
            ulonglong2 a23 = *(const ulonglong2*)&As[cur][k][tm + 4];
            float4 b0 = *(const float4*)&Bs[cur][k][tn];
            float4 b1 = *(const float4*)&Bs[cur][k][tn + 4];
            float bj[8] = {b0.x, b0.y, b0.z, b0.w, b1.x, b1.y, b1.z, b1.w};
            #pragma unroll
            for (int j = 0; j < 8; ++j) {
                ull bd = dup2(bj[j]);
                acc[0][j] = ffma2(a01.x, bd, acc[0][j]);
                acc[1][j] = ffma2(a01.y, bd, acc[1][j]);
                acc[2][j] = ffma2(a23.x, bd, acc[2][j]);
                acc[3][j] = ffma2(a23.y, bd, acc[3][j]);
            }
        }
        if (kc < 15) {
            int nb = cur ^ 1;
            #pragma unroll
            for (int i = 0; i < 2; ++i) {
                int r = lr + (i << 6);
                As[nb][lk+0][r] = pa[i].x; As[nb][lk+1][r] = pa[i].y;
                As[nb][lk+2][r] = pa[i].z; As[nb][lk+3][r] = pa[i].w;
                Bs[nb][lk+0][r] = pb[i].x; Bs[nb][lk+1][r] = pb[i].y;
                Bs[nb][lk+2][r] = pb[i].z; Bs[nb][lk+3][r] = pb[i].w;
            }
            __syncthreads();
        }
    }
    #pragma unroll
    for (int mp = 0; mp < 4; ++mp) {
        float r0[8], r1[8];
        #pragma unroll
        for (int j = 0; j < 8; ++j) {
            float2 t = unpack2(acc[mp][j]);
            r0[j] = t.x; r1[j] = t.y;
        }
        float* p0p = g_qkv + (size_t)(m0 + tm + 2 * mp) * 768 + n0 + tn;
        *(float4*)p0p       = make_float4(r0[0], r0[1], r0[2], r0[3]);
        *(float4*)(p0p + 4) = make_float4(r0[4], r0[5], r0[6], r0[7]);
        *(float4*)(p0p + 768)     = make_float4(r1[0], r1[1], r1[2], r1[3]);
        *(float4*)(p0p + 768 + 4) = make_float4(r1[4], r1[5], r1[6], r1[7]);
    }
}

// ---------------- permute proj weights: k' = br*128 + head*32 + ci <- c = br*128 + ci*4 + head
__global__ void permw_kernel(const float* __restrict__ pw) {
    int n = blockIdx.x, k = threadIdx.x;
    int br = k >> 7, r = k & 127, h = r >> 5, ci = r & 31;
    g_pw2[n * 256 + k] = pw[n * 256 + br * 128 + ci * 4 + h];
}

// ---------------- Kernel 4: proj GEMM (f32x2, double-buffered) ----------------
// out[(bb*256+n)*4096 + p] = sum_k' g_xcat2[(bb*4096+p)*256 + k'] * g_pw2[n*256+k'] + PB[n]
__global__ __launch_bounds__(256, 2) void gemm_proj(const float* __restrict__ PB,
                                                    float* __restrict__ out) {
    __shared__ float As[2][16][128];
    __shared__ float Bs[2][16][128];
    int n0 = blockIdx.x << 7;
    int m0 = blockIdx.y << 7;             // global token
    int bb = m0 >> 12, p0 = m0 & 4095;
    int tid = threadIdx.x;
    int tm = (tid >> 4) << 3, tn = (tid & 15) << 3;
    int lr = tid >> 2, lk = (tid & 3) << 2;
    ull acc[4][8];
    #pragma unroll
    for (int i = 0; i < 4; ++i)
        #pragma unroll
        for (int j = 0; j < 8; ++j) acc[i][j] = 0ull;

    const float* Ab = g_xcat2 + (size_t)m0 * 256;
    const float* Bb = g_pw2   + (size_t)n0 * 256;

    #pragma unroll
    for (int i = 0; i < 2; ++i) {
        int r = lr + (i << 6);
        float4 va = *(const float4*)(Ab + (size_t)r * 256 + lk);
        As[0][lk+0][r] = va.x; As[0][lk+1][r] = va.y; As[0][lk+2][r] = va.z; As[0][lk+3][r] = va.w;
        float4 vb = *(const float4*)(Bb + (size_t)r * 256 + lk);
        Bs[0][lk+0][r] = vb.x; Bs[0][lk+1][r] = vb.y; Bs[0][lk+2][r] = vb.z; Bs[0][lk+3][r] = vb.w;
    }
    __syncthreads();

    for (int kc = 0; kc < 16; ++kc) {
        int cur = kc & 1;
        float4 pa[2], pb[2];
        if (kc < 15) {
            int k0 = (kc + 1) << 4;
            #pragma unroll
            for (int i = 0; i < 2; ++i) {
                int r = lr + (i << 6);
                pa[i] = *(const float4*)(Ab + (size_t)r * 256 + k0 + lk);
                pb[i] = *(const float4*)(Bb + (size_t)r * 256 + k0 + lk);
            }
        }
        #pragma unroll
        for (int k = 0; k < 16; ++k) {
            ulonglong2 a01 = *(const ulonglong2*)&As[cur][k][tm];
            ulonglong2 a23 = *(const ulonglong2*)&As[cur][k][tm + 4];
            float4 b0 = *(const float4*)&Bs[cur][k][tn];
            float4 b1 = *(const float4*)&Bs[cur][k][tn + 4];
            float bj[8] = {b0.x, b0.y, b0.z, b0.w, b1.x, b1.y, b1.z, b1.w};
            #pragma unroll
            for (int j = 0; j < 8; ++j) {
                ull bd = dup2(bj[j]);
                acc[0][j] = ffma2(a01.x, bd, acc[0][j]);
                acc[1][j] = ffma2(a01.y, bd, acc[1][j]);
                acc[2][j] = ffma2(a23.x, bd, acc[2][j]);
                acc[3][j] = ffma2(a23.y, bd, acc[3][j]);
            }
        }
        if (kc < 15) {
            int nb = cur ^ 1;
            #pragma unroll
            for (int i = 0; i < 2; ++i) {
                int r = lr + (i << 6);
                As[nb][lk+0][r] = pa[i].x; As[nb][lk+1][r] = pa[i].y;
                As[nb][lk+2][r] = pa[i].z; As[nb][lk+3][r] = pa[i].w;
                Bs[nb][lk+0][r] = pb[i].x; Bs[nb][lk+1][r] = pb[i].y;
                Bs[nb][lk+2][r] = pb[i].z; Bs[nb][lk+3][r] = pb[i].w;
            }
            __syncthreads();
        }
    }
    // epilogue: rows = channels (n), cols = tokens (p); out is channel-major
    #pragma unroll
    for (int j = 0; j < 8; ++j) {
        int n = n0 + tn + j;
        float pbv = PB[n];
        float2 t0 = unpack2(acc[0][j]);
        float2 t1 = unpack2(acc[1][j]);
        float2 t2 = unpack2(acc[2][j]);
        float2 t3 = unpack2(acc[3][j]);
        float* cp = out + (size_t)(bb * 256 + n) * 4096 + p0 + tm;
        *(float4*)cp       = make_float4(t0.x + pbv, t0.y + pbv, t1.x + pbv, t1.y + pbv);
        *(float4*)(cp + 4) = make_float4(t2.x + pbv, t2.y + pbv, t3.x + pbv, t3.y + pbv);
    }
}

// ---------------- Kernel 3: stripe-window attention + LePE (f32x2) ----------------
__global__ __launch_bounds__(256) void attn_kernel(
        const float* __restrict__ lw1, const float* __restrict__ lb1,
        const float* __restrict__ lw2, const float* __restrict__ lb2,
        float* attnOut0, float* attnOut1) {
    extern __shared__ float sm[];
    float* Ks    = sm;          // 8192 floats [s][ci]
    float* Vs    = sm + 8192;   // 8192
    float* stage = sm + 16384;  // 256*17
    float* rinv  = sm + 20736;  // 256
    float* wleT  = sm + 20992;  // 9*32
    float* blep  = sm + 21280;  // 32

    int blk    = blockIdx.x;
    int branch = blk >> 9;
    int rem    = blk & 511;
    int bw     = rem >> 2;
    int head   = rem & 3;
    int bb     = bw >> 4;
    int widx   = bw & 15;
    int tid    = threadIdx.x;
    int cbase  = branch * 128 + head;

    for (int e = tid; e < 8192; e += 256) {
        int s = e >> 5, ci = e & 31;
        int l = (branch == 0) ? ((s >> 2) * 64 + widx * 4 + (s & 3))
                              : ((widx * 4 + (s >> 6)) * 64 + (s & 63));
        const float* rp = g_qkv + (size_t)(bb * 4096 + l) * 768 + cbase + ci * 4;
        Ks[e] = rp[256];
        Vs[e] = rp[512];
    }
    const float* lw = branch ? lw2 : lw1;
    const float* lb = branch ? lb2 : lb1;
    for (int e = tid; e < 288; e += 256) {
        int kk = e >> 5, ci = e & 31;
        wleT[e] = lw[(ci * 4 + head) * 9 + kk];
    }
    if (tid < 32) blep[tid] = lb[tid * 4 + head];

    int lq = (branch == 0) ? ((tid >> 2) * 64 + widx * 4 + (tid & 3))
                           : ((widx * 4 + (tid >> 6)) * 64 + (tid & 63));
    const float* qp = g_qkv + (size_t)(bb * 4096 + lq) * 768 + cbase;
    ull q2[16];
    #pragma unroll
    for (int u = 0; u < 16; ++u)
        q2[u] = pack2(qp[(2 * u) * 4] * 0.125f, qp[(2 * u + 1) * 4] * 0.125f);
    __syncthreads();

    float* attnRow = (branch ? (attnOut1 ? attnOut1 : g_attn_fb + 33554432)
                             : (attnOut0 ? attnOut0 : g_attn_fb))
                     + (size_t)(bw * 4 + head) * 65536;

    ull o2[16];
    #pragma unroll
    for (int u = 0; u < 16; ++u) o2[u] = 0ull;
    float ssum = 0.f;

    for (int ch = 0; ch < 16; ++ch) {
        float ebuf[16];
        #pragma unroll
        for (int jj = 0; jj < 16; ++jj) {
            int j = (ch << 4) + jj;
            const ulonglong2* kr = (const ulonglong2*)(Ks + j * 32);
            ull d2a = 0ull, d2b = 0ull;
            #pragma unroll
            for (int u = 0; u < 8; ++u) {
                ulonglong2 kk = kr[u];
                d2a = ffma2(q2[2 * u],     kk.x, d2a);
                d2b = ffma2(q2[2 * u + 1], kk.y, d2b);
            }
            float2 da = unpack2(d2a), db = unpack2(d2b);
            float e = __expf((da.x + db.x) + (da.y + db.y));   // logits O(0.1): no max-shift
            ssum += e;
            ebuf[jj] = e;
            ull e2 = dup2(e);
            const ulonglong2* vr = (const ulonglong2*)(Vs + j * 32);
            #pragma unroll
            for (int u = 0; u < 8; ++u) {
                ulonglong2 vv = vr[u];
                o2[2 * u]     = ffma2(e2, vv.x, o2[2 * u]);
                o2[2 * u + 1] = ffma2(e2, vv.y, o2[2 * u + 1]);
            }
        }
        #pragma unroll
        for (int jj = 0; jj < 16; ++jj) stage[tid * 17 + jj] = ebuf[jj];
        __syncthreads();
        #pragma unroll
        for (int i = 0; i < 16; ++i) {
            int idx = tid + (i << 8);
            int ss = idx >> 4, jj = idx & 15;
            attnRow[ss * 256 + (ch << 4) + jj] = stage[ss * 17 + jj];
        }
        __syncthreads();
    }

    // normalize attn in place (coalesced float4 pass)
    float is = 1.f / ssum;
    rinv[tid] = is;
    __syncthreads();
    float4* a4 = (float4*)attnRow;
    for (int i = 0; i < 64; ++i) {
        int idx = tid + (i << 8);
        float r = rinv[idx >> 6];
        float4 vv = a4[idx];
        vv.x *= r; vv.y *= r; vv.z *= r; vv.w *= r;
        a4[idx] = vv;
    }

    // LePE (depthwise 3x3 on window image), f32x2
    int y, x, Wimg, Himg;
    if (branch == 0) { y = tid >> 2; x = tid & 3;  Wimg = 4;  Himg = 64; }
    else             { y = tid >> 6; x = tid & 63; Wimg = 64; Himg = 4;  }
    ull lep2[16];
    #pragma unroll
    for (int u = 0; u < 8; ++u) {
        ulonglong2 bv = ((const ulonglong2*)blep)[u];
        lep2[2 * u] = bv.x; lep2[2 * u + 1] = bv.y;
    }
    #pragma unroll
    for (int ky = 0; ky < 3; ++ky) {
        int yy = y + ky - 1;
        if (yy < 0 || yy >= Himg) continue;
        #pragma unroll
        for (int kx = 0; kx < 3; ++kx) {
            int xx = x + kx - 1;
            if (xx < 0 || xx >= Wimg) continue;
            int sp = yy * Wimg + xx;
            const ulonglong2* vv = (const ulonglong2*)(Vs + sp * 32);
            const ulonglong2* wr = (const ulonglong2*)(wleT + (ky * 3 + kx) * 32);
            #pragma unroll
            for (int u = 0; u < 8; ++u) {
                ulonglong2 w4 = wr[u];
                ulonglong2 vu = vv[u];
                lep2[2 * u]     = ffma2(w4.x, vu.x, lep2[2 * u]);
                lep2[2 * u + 1] = ffma2(w4.y, vu.y, lep2[2 * u + 1]);
            }
        }
    }

    // staged coalesced epilogue into token-major, head-grouped g_xcat2
    __syncthreads();                 // all Ks/Vs reads complete
    float* ostage = sm;              // stride 33, 8448 floats (overlaps dead Ks/Vs)
    #pragma unroll
    for (int u = 0; u < 16; ++u) {
        float2 ov = unpack2(o2[u]);
        float2 lv = unpack2(lep2[u]);
        ostage[tid * 33 + 2 * u + 0] = ov.x * is + lv.x;
        ostage[tid * 33 + 2 * u + 1] = ov.y * is + lv.y;
    }
    __syncthreads();
    int cb2 = branch * 128 + head * 32;
    for (int i = 0; i < 32; ++i) {
        int idx = tid + (i << 8);
        int so = idx >> 5, c = idx & 31;
        int pos = (branch == 0) ? ((so >> 2) * 64 + widx * 4 + (so & 3))
                                : ((widx * 4 + (so >> 6)) * 64 + (so & 63));
        g_xcat2[(size_t)(bb * 4096 + pos) * 256 + cb2 + c] = ostage[so * 33 + c];
    }
}

// ---------------- launcher ----------------
extern "C" void kernel_launch(void* const* d_in, const int* in_sizes, int n_in,
                              void* d_out, int out_size) {
    const float* x       = (const float*)d_in[0];
    const float* ln_g    = (const float*)d_in[1];
    const float* ln_b    = (const float*)d_in[2];
    const float* w_qkv   = (const float*)d_in[3];
    const float* proj_w  = (const float*)d_in[4];
    const float* proj_b  = (const float*)d_in[5];
    const float* lepe_w1 = (const float*)d_in[6];
    const float* lepe_b1 = (const float*)d_in[7];
    const float* lepe_w2 = (const float*)d_in[8];
    const float* lepe_b2 = (const float*)d_in[9];
    float* out = (float*)d_out;

    float* a0 = nullptr; float* a1 = nullptr;
    if (out_size >= 75497472) { a0 = out + 8388608; a1 = a0 + 33554432; }

    const int ATTN_SMEM = 21312 * 4;
    cudaFuncSetAttribute(attn_kernel, cudaFuncAttributeMaxDynamicSharedMemorySize, ATTN_SMEM);

    ln_kernel<<<1024, dim3(32, 32)>>>(x, ln_g, ln_b);
    permw_kernel<<<256, 256>>>(proj_w);
    gemm_qkv<<<dim3(6, 256), 256>>>(w_qkv);
    attn_kernel<<<1024, 256, ATTN_SMEM>>>(lepe_w1, lepe_b1, lepe_w2, lepe_b2, a0, a1);
    gemm_proj<<<dim3(2, 256), 256>>>(proj_b, out);
}